// round 14
// baseline (speedup 1.0000x reference)
#include <cuda_runtime.h>
#include <cuda_bf16.h>

// QuantumConv2d on GB300 — direct tensor-product RX application (no WHT, no smem).
//
// Per 2x2 patch (x0,x1,x2,x3):
//   t_k = +-x0 +-x1 +-x2 +-x3  (sign + iff bit q of k set, LSB-first)
//   t_{15-k} = -t_k  ->  share u = -t^2/4:  ph_k = u - t/2,  ph_{15-k} = u + t/2
//   d_k = exp(i ph_k)
//   y = (RX(w3)(x)RX(w2)(x)RX(w1)(x)RX(w0)) d as 4 commuting single-qubit
//       stages: pair (a, b=a^2^q): y_a = c a - i s b, y_b = -i s a + c b.
//       Packed (re,im): -i s b = (s*bi, -s*br) = (s,-s) .* swap(b)
//   0.25 initial-state amplitude folded into stage-3 coefficients.
//   state_{F(j)} = y_j, F = CNOT-ring perm {0,14,15,1,13,3,2,12,9,7,6,8,4,10,11,5}
//   out_q = sum_{j: bit(3-q) of F(j)} |y_j|^2, accumulated as packed
//   FMA2(v,v,acc) per group (2 accumulators/group, depth 3).
//
// Session law (R8/R9/R10/R12): keep the graph wide & shallow; pack only where
// data already lives as aligned complex pairs. R14 removes ~31 fma-pipe ops
// ( +-pair phase sharing, FMA2-accumulated epilogue ) with no shape change.

#define PK2(d, lo, hi)   asm("mov.b64 %0, {%1, %2};" : "=l"(d) : "f"(lo), "f"(hi))
#define UPK2(lo, hi, d)  asm("mov.b64 {%0, %1}, %2;" : "=f"(lo), "=f"(hi) : "l"(d))
#define MUL2(d, a, b)    asm("mul.rn.f32x2 %0, %1, %2;" : "=l"(d) : "l"(a), "l"(b))
#define FMA2(d, a, b, c) asm("fma.rn.f32x2 %0, %1, %2, %3;" : "=l"(d) : "l"(a), "l"(b), "l"(c))

#define TPB 128

__global__ __launch_bounds__(TPB) void qconv_kernel(const float* __restrict__ x,
                                                    const float* __restrict__ w,
                                                    float4* __restrict__ out) {
    // per-thread RX coefficients (w is uniform -> L1/L2 cached)
    float c[4], s[4];
    #pragma unroll
    for (int q = 0; q < 4; q++)
        __sincosf(0.5f * w[q], &s[q], &c[q]);
    c[3] *= 0.25f;   // fold |psi0| amplitude into last stage
    s[3] *= 0.25f;

    int tid = blockIdx.x * TPB + threadIdx.x;   // = b*16384 + jj*128 + ii
    int b  = tid >> 14;
    int jj = (tid >> 7) & 127;
    int ii = tid & 127;

    const float* p = x + (b << 16) + (jj << 9) + (ii << 1);
    float2 a01 = *(const float2*)(p);
    float2 a23 = *(const float2*)(p + 256);
    float x0 = a01.x, x1 = a01.y, x2 = a23.x, x3 = a23.y;

    // t_k for k=0..7 from P/M/Q/R; k=8..15 are negations (handled via ph = u +- t/2)
    float P = x0 + x1, M = x0 - x1, Q = x2 + x3, R = x2 - x3;
    float t[8];
    t[0] = -P - Q;  t[1] =  M - Q;  t[2] = -M - Q;  t[3] =  P - Q;
    t[4] =  R - P;  t[5] =  M + R;  t[6] =  R - M;  t[7] =  P + R;

    // phases + cis: per pair (k, 15-k) share u = -t^2/4
    unsigned long long v[16];   // packed (re, im)
    #pragma unroll
    for (int k = 0; k < 8; k++) {
        float tk = t[k];
        float u  = tk * (-0.25f * tk);        // -t^2/4
        float pha = fmaf(-0.5f, tk, u);       // ph_k      = u - t/2
        float phb = fmaf( 0.5f, tk, u);       // ph_{15-k} = u + t/2
        float sa, ca, sb, cb;
        __sincosf(pha, &sa, &ca);
        __sincosf(phb, &sb, &cb);
        PK2(v[k],      ca, sa);
        PK2(v[15 - k], cb, sb);
    }

    // 4 single-qubit RX stages (commuting), packed complex — R11 form
    #pragma unroll
    for (int q = 0; q < 4; q++) {
        int m = 1 << q;
        float cq = c[q], sq = s[q], nsq = -s[q];
        unsigned long long C2, S2;
        PK2(C2, cq, cq);      // (c,  c)
        PK2(S2, sq, nsq);     // (s, -s)
        #pragma unroll
        for (int k = 0; k < 16; k++) {
            if (!(k & m)) {
                unsigned long long a = v[k], bb = v[k | m];
                float ar, ai, br, bi;
                UPK2(ar, ai, a);
                UPK2(br, bi, bb);
                unsigned long long sa, sb;        // swapped halves (ALU MOVs)
                PK2(sa, ai, ar);
                PK2(sb, bi, br);
                unsigned long long ta, tb, ya, yb;
                MUL2(ta, a, C2);
                MUL2(tb, bb, C2);
                FMA2(ya, sb, S2, ta);             // c*a + (s*bi, -s*br)
                FMA2(yb, sa, S2, tb);             // c*b + (s*ai, -s*ar)
                v[k] = ya; v[k | m] = yb;
            }
        }
    }

    // grouped |.|^2 accumulation through F = {0,14,15,1,13,3,2,12,9,7,6,8,4,10,11,5}
    // each group: two depth-2 FMA2 accumulators + 1 ADD2 (wide across 6 groups)
    #define GRP(res, iA, iB, iC, iD) do {                        \
        unsigned long long a1, a2;                               \
        MUL2(a1, v[iA], v[iA]);  FMA2(a1, v[iB], v[iB], a1);     \
        MUL2(a2, v[iC], v[iC]);  FMA2(a2, v[iD], v[iD], a2);     \
        ADD2(res, a1, a2);                                       \
    } while (0)
    #define ADD2(d, a, b) asm("add.rn.f32x2 %0, %1, %2;" : "=l"(d) : "l"(a), "l"(b))

    unsigned long long T1p, T2p, T3p, U1p, U2p, U3p;
    GRP(T1p, 9, 10, 12, 15);
    GRP(T2p, 8, 11, 13, 14);
    GRP(T3p, 1, 2, 4, 7);
    GRP(U1p, 3, 4, 8, 15);
    GRP(U2p, 1, 6, 10, 13);
    GRP(U3p, 2, 5, 9, 14);

    unsigned long long o0p, o1p, o2p, o3p;
    ADD2(o0p, T2p, T3p);   // bit 3 of F(j)
    ADD2(o1p, T1p, T3p);   // bit 2
    ADD2(o2p, U2p, U3p);   // bit 1
    ADD2(o3p, U1p, U3p);   // bit 0

    float lo, hi;
    float4 o;
    UPK2(lo, hi, o0p); o.x = lo + hi;
    UPK2(lo, hi, o1p); o.y = lo + hi;
    UPK2(lo, hi, o2p); o.z = lo + hi;
    UPK2(lo, hi, o3p); o.w = lo + hi;

    out[tid] = o;
}

extern "C" void kernel_launch(void* const* d_in, const int* in_sizes, int n_in,
                              void* d_out, int out_size) {
    const float* x = (const float*)d_in[0];
    const float* w = (const float*)d_in[1];
    if (n_in >= 2 && in_sizes[0] == 4) {   // robustness if metadata order differs
        x = (const float*)d_in[1];
        w = (const float*)d_in[0];
    }
    qconv_kernel<<<8192, TPB>>>(x, w, (float4*)d_out);
}

// round 15
// speedup vs baseline: 1.1388x; 1.1388x over previous
#include <cuda_runtime.h>
#include <cuda_bf16.h>

// QuantumConv2d on GB300 — direct tensor-product RX, 2 patches/thread.
//
// Per 2x2 patch (x0,x1,x2,x3):
//   t_k = A[k&3] + B[k>>2]  (signed sums, sign + iff bit set, LSB-first)
//   phase_k = -(t/2 + t^2/4)          [global phase dropped]
//   d_k = exp(i phase_k)
//   y = (RX(w3)(x)RX(w2)(x)RX(w1)(x)RX(w0)) d as 4 commuting single-qubit
//       stages: pair (a, b=a^2^q): y_a = c a - i s b, y_b = -i s a + c b.
//       Packed (re,im): -i s b = (s*bi, -s*br) = (s,-s) .* swap(b)
//   0.25 initial-state amplitude folded into stage-3 coefficients.
//   state_{F(j)} = y_j, F = CNOT-ring perm {0,14,15,1,13,3,2,12,9,7,6,8,4,10,11,5}
//   out_q = sum_{j: bit(3-q) of F(j)} |y_j|^2
//
// R13/R14 falsified the fma-throughput-floor model (op cuts didn't move time;
// fma pipe only ~62% busy) -> stall-bound: warps are phase-locked, so the
// 32-MUFU sincos burst starves the fma pipe and vice versa. R15: TWO patches
// per thread in one straight-line block — ptxas interleaves patch B's MUFU
// with patch A's FMA stages (guaranteed intra-warp overlap), amortizes setup,
// and halves load count (adjacent patches -> float4 loads).

#define PK2(d, lo, hi)   asm("mov.b64 %0, {%1, %2};" : "=l"(d) : "f"(lo), "f"(hi))
#define UPK2(lo, hi, d)  asm("mov.b64 {%0, %1}, %2;" : "=f"(lo), "=f"(hi) : "l"(d))
#define MUL2(d, a, b)    asm("mul.rn.f32x2 %0, %1, %2;" : "=l"(d) : "l"(a), "l"(b))
#define FMA2(d, a, b, c) asm("fma.rn.f32x2 %0, %1, %2, %3;" : "=l"(d) : "l"(a), "l"(b), "l"(c))

#define TPB 128

// R11 math body for one patch; inlined twice so ptxas can interleave the two
// copies (MUFU of one overlapping FMA of the other).
__device__ __forceinline__ float4 qpatch(float x0, float x1, float x2, float x3,
                                         const float c[4], const float s[4]) {
    float A[4] = {-x0 - x1,  x0 - x1, -x0 + x1,  x0 + x1};
    float B[4] = {-x2 - x3,  x2 - x3, -x2 + x3,  x2 + x3};

    // phases + cis (scalar — measured best)
    unsigned long long v[16];   // packed (re, im)
    #pragma unroll
    for (int k = 0; k < 16; k++) {
        float t  = A[k & 3] + B[k >> 2];
        float ph = t * fmaf(-0.25f, t, -0.5f);   // -(t/2 + t^2/4)
        float sn, cs;
        __sincosf(ph, &sn, &cs);
        PK2(v[k], cs, sn);
    }

    // 4 single-qubit RX stages (commuting), packed complex
    #pragma unroll
    for (int q = 0; q < 4; q++) {
        int m = 1 << q;
        float cq = c[q], sq = s[q], nsq = -s[q];
        unsigned long long C2, S2;
        PK2(C2, cq, cq);      // (c,  c)
        PK2(S2, sq, nsq);     // (s, -s)
        #pragma unroll
        for (int k = 0; k < 16; k++) {
            if (!(k & m)) {
                unsigned long long a = v[k], bb = v[k | m];
                float ar, ai, br, bi;
                UPK2(ar, ai, a);
                UPK2(br, bi, bb);
                unsigned long long sa, sb;        // swapped halves (ALU MOVs)
                PK2(sa, ai, ar);
                PK2(sb, bi, br);
                unsigned long long ta, tb, ya, yb;
                MUL2(ta, a, C2);
                MUL2(tb, bb, C2);
                FMA2(ya, sb, S2, ta);             // c*a + (s*bi, -s*br)
                FMA2(yb, sa, S2, tb);             // c*b + (s*ai, -s*ar)
                v[k] = ya; v[k | m] = yb;
            }
        }
    }

    // probabilities (scalar, wide ILP)
    float pr[16];
    #pragma unroll
    for (int j = 0; j < 16; j++) {
        float re, im;
        UPK2(re, im, v[j]);
        pr[j] = fmaf(re, re, im * im);
    }

    // grouped accumulation through F = {0,14,15,1,13,3,2,12,9,7,6,8,4,10,11,5}
    float T1 = pr[9]  + pr[10] + pr[12] + pr[15];
    float T2 = pr[8]  + pr[11] + pr[13] + pr[14];
    float T3 = pr[1]  + pr[2]  + pr[4]  + pr[7];
    float U1 = pr[3]  + pr[4]  + pr[8]  + pr[15];
    float U2 = pr[1]  + pr[6]  + pr[10] + pr[13];
    float U3 = pr[2]  + pr[5]  + pr[9]  + pr[14];
    return make_float4(T2 + T3,   // bit 3 of F(j)
                       T1 + T3,   // bit 2
                       U2 + U3,   // bit 1
                       U1 + U3);  // bit 0
}

__global__ __launch_bounds__(TPB) void qconv_kernel(const float* __restrict__ x,
                                                    const float* __restrict__ w,
                                                    float4* __restrict__ out) {
    // per-thread RX coefficients, amortized over 2 patches
    float c[4], s[4];
    #pragma unroll
    for (int q = 0; q < 4; q++)
        __sincosf(0.5f * w[q], &s[q], &c[q]);
    c[3] *= 0.25f;   // fold |psi0| amplitude into last stage
    s[3] *= 0.25f;

    int gtid = blockIdx.x * TPB + threadIdx.x;   // handles patches 2*gtid, 2*gtid+1
    int b  = gtid >> 13;
    int jj = (gtid >> 6) & 127;
    int e  = gtid & 63;                          // ii pair = (2e, 2e+1)

    // patch pair spans cols 4e..4e+3 of rows 2jj, 2jj+1 -> two float4 loads
    const float* p = x + (b << 16) + (jj << 9) + (e << 2);
    float4 r0 = *(const float4*)(p);             // row 2jj
    float4 r1 = *(const float4*)(p + 256);       // row 2jj+1

    // patch A: (r0.x, r0.y, r1.x, r1.y); patch B: (r0.z, r0.w, r1.z, r1.w)
    float4 oA = qpatch(r0.x, r0.y, r1.x, r1.y, c, s);
    float4 oB = qpatch(r0.z, r0.w, r1.z, r1.w, c, s);

    out[2 * gtid]     = oA;
    out[2 * gtid + 1] = oB;
}

extern "C" void kernel_launch(void* const* d_in, const int* in_sizes, int n_in,
                              void* d_out, int out_size) {
    const float* x = (const float*)d_in[0];
    const float* w = (const float*)d_in[1];
    if (n_in >= 2 && in_sizes[0] == 4) {   // robustness if metadata order differs
        x = (const float*)d_in[1];
        w = (const float*)d_in[0];
    }
    qconv_kernel<<<4096, TPB>>>(x, w, (float4*)d_out);
}